// round 5
// baseline (speedup 1.0000x reference)
#include <cuda_runtime.h>
#include <cuda_bf16.h>
#include <cstdint>

#define BATCH    256
#define EMB      512
#define NCLS     100000
#define N_TILE   96          // weight rows per CTA (32 classes)
#define CLS_TILE 32
#define NCTAS    3125
#define KCH      64          // K per chunk
#define NCHUNKS  8

// SMEM layout (bytes). Row stride 144B (64 bf16 = 128B + 16B pad): 16B-aligned
// for cp.async, and 144/4=36 ≡ 4 (mod 32) words keeps LDS fragment loads
// conflict-free.
#define AS        144
#define A_BUF     (256 * AS)             // 36864
#define B_BUF     (96 * AS)              // 13824
#define SMEM_INV  0                      // 96 floats
#define SMEM_BUF  512
#define OFF_A0    (SMEM_BUF)
#define OFF_A1    (SMEM_BUF + A_BUF)
#define OFF_B0    (SMEM_BUF + 2 * A_BUF)
#define OFF_B1    (SMEM_BUF + 2 * A_BUF + B_BUF)
#define COS_STRIDE 97                    // floats
#define COS_BYTES  (256 * COS_STRIDE * 4)      // 99328, union with GEMM bufs
#define GEMM_BYTES (2 * A_BUF + 2 * B_BUF)     // 101376
#define SMEM_TOTAL (SMEM_BUF + (COS_BYTES > GEMM_BYTES ? COS_BYTES : GEMM_BYTES))

// device scratch (no runtime allocation)
__device__ __align__(128) __nv_bfloat16 g_Ebf[BATCH * EMB];
__device__ float g_Spart[(size_t)NCTAS * BATCH];
__device__ float g_LL[BATCH];
__device__ float g_loss[BATCH];

// ---------------- helpers ----------------
__device__ __forceinline__ void cp_async16(uint32_t smem_dst, const void* gsrc) {
    asm volatile("cp.async.cg.shared.global [%0], [%1], 16;" :: "r"(smem_dst), "l"(gsrc));
}
#define CP_COMMIT() asm volatile("cp.async.commit_group;" ::: "memory")
#define CP_WAIT0()  asm volatile("cp.async.wait_group 0;" ::: "memory")

__device__ __forceinline__ void mma_bf16(float& d0, float& d1, float& d2, float& d3,
                                         uint32_t a0, uint32_t a1, uint32_t a2, uint32_t a3,
                                         uint32_t b0, uint32_t b1) {
    asm volatile("mma.sync.aligned.m16n8k16.row.col.f32.bf16.bf16.f32 "
                 "{%0,%1,%2,%3}, {%4,%5,%6,%7}, {%8,%9}, {%0,%1,%2,%3};"
                 : "+f"(d0), "+f"(d1), "+f"(d2), "+f"(d3)
                 : "r"(a0), "r"(a1), "r"(a2), "r"(a3), "r"(b0), "r"(b1));
}

// exp(64*(c-1)) via exp2 with degree-7 FFMA polynomial (no MUFU)
__device__ __forceinline__ float expshift(float c) {
    float x = 92.33248261689366f * (c - 1.0f);   // 64*log2(e)*(c-1), <= 0
    float t = fmaxf(x, -126.0f);
    float fl = floorf(t);
    float f = t - fl;
    float p = 1.5252733804059841e-5f;
    p = fmaf(p, f, 1.5403530393381608e-4f);
    p = fmaf(p, f, 1.3333558146428443e-3f);
    p = fmaf(p, f, 9.618129107628477e-3f);
    p = fmaf(p, f, 5.550410866482158e-2f);
    p = fmaf(p, f, 2.402265069591007e-1f);
    p = fmaf(p, f, 6.931471805599453e-1f);
    p = fmaf(p, f, 1.0f);
    return p * __int_as_float(((int)fl + 127) << 23);
}

// ---------------- kernel 1: normalize embeddings -> bf16 ----------------
__global__ void __launch_bounds__(128) k_norm_e(const float* __restrict__ E) {
    int n = blockIdx.x, tid = threadIdx.x;
    float4 v = *reinterpret_cast<const float4*>(E + n * EMB + tid * 4);
    float ss = v.x * v.x + v.y * v.y + v.z * v.z + v.w * v.w;
    ss += __shfl_xor_sync(0xffffffffu, ss, 16);
    ss += __shfl_xor_sync(0xffffffffu, ss, 8);
    ss += __shfl_xor_sync(0xffffffffu, ss, 4);
    ss += __shfl_xor_sync(0xffffffffu, ss, 2);
    ss += __shfl_xor_sync(0xffffffffu, ss, 1);
    __shared__ float ws[4];
    if ((tid & 31) == 0) ws[tid >> 5] = ss;
    __syncthreads();
    float inv = 1.0f / fmaxf(sqrtf(ws[0] + ws[1] + ws[2] + ws[3]), 1e-12f);
    uint32_t p0, p1;
    asm("cvt.rn.bf16x2.f32 %0, %1, %2;" : "=r"(p0) : "f"(v.y * inv), "f"(v.x * inv));
    asm("cvt.rn.bf16x2.f32 %0, %1, %2;" : "=r"(p1) : "f"(v.w * inv), "f"(v.z * inv));
    reinterpret_cast<uint2*>(g_Ebf)[n * (EMB / 4) + tid] = make_uint2(p0, p1);
}

// ---------------- kernel 2: GEMM (mma.sync bf16) + fused ArcFace epilogue ----
__global__ void __launch_bounds__(256) k_main(const float* __restrict__ W,
                                              const int* __restrict__ labels32) {
    extern __shared__ char smem[];
    const int tid = threadIdx.x;
    const int w = tid >> 5, l = tid & 31;
    const int cta = blockIdx.x;

    // ---- label dtype probe: int64 iff all odd 32-bit words in first 1024B are 0
    int oddv = (tid < 128) ? labels32[2 * tid + 1] : 0;
    int is64 = (__syncthreads_or(oddv) == 0);

    const int col4 = tid & 15;       // float4 column within K-chunk
    const int rb = tid >> 4;         // row base
    const float4* __restrict__ Wf4 = reinterpret_cast<const float4*>(W);

    float ssq[6];
#pragma unroll
    for (int i = 0; i < 6; i++) ssq[i] = 0.0f;

    float acc[2][12][4];
#pragma unroll
    for (int mi = 0; mi < 2; mi++)
#pragma unroll
        for (int ni = 0; ni < 12; ni++)
#pragma unroll
            for (int k = 0; k < 4; k++) acc[mi][ni][k] = 0.0f;

    // ---- A copy (cp.async): thread t copies sample row t, 8x16B per chunk
    auto issueA = [&](int c, int buf) {
        uint32_t dst = (uint32_t)__cvta_generic_to_shared(
            smem + (buf ? OFF_A1 : OFF_A0) + tid * AS);
        const char* src = reinterpret_cast<const char*>(g_Ebf) + ((size_t)tid * EMB + c * KCH) * 2;
#pragma unroll
        for (int j = 0; j < 8; j++) cp_async16(dst + j * 16, src + j * 16);
    };
    // ---- B prefetch to regs
    float4 bp[6];
    auto ldgB = [&](int c) {
#pragma unroll
        for (int i = 0; i < 6; i++) {
            size_t row = (size_t)cta * N_TILE + rb + i * 16;
            bp[i] = Wf4[row * 128 + c * 16 + col4];
        }
    };
    // ---- B store to smem (cvt + ssq accumulate)
    auto stsB = [&](int buf) {
        char* base = smem + (buf ? OFF_B1 : OFF_B0);
#pragma unroll
        for (int i = 0; i < 6; i++) {
            float4 v = bp[i];
            ssq[i] = fmaf(v.x, v.x, fmaf(v.y, v.y, fmaf(v.z, v.z, fmaf(v.w, v.w, ssq[i]))));
            uint32_t p0, p1;
            asm("cvt.rn.bf16x2.f32 %0, %1, %2;" : "=r"(p0) : "f"(v.y), "f"(v.x));
            asm("cvt.rn.bf16x2.f32 %0, %1, %2;" : "=r"(p1) : "f"(v.w), "f"(v.z));
            *reinterpret_cast<uint2*>(base + (rb + i * 16) * AS + col4 * 8) = make_uint2(p0, p1);
        }
    };

    // prologue: chunk 0
    issueA(0, 0);
    CP_COMMIT();
    ldgB(0);
    stsB(0);
    CP_WAIT0();
    __syncthreads();

    const int arow = w * 32 + (l >> 2);
    const int acol = (l & 3) * 2;

    for (int c = 0; c < NCHUNKS; c++) {
        int b = c & 1;
        if (c < NCHUNKS - 1) {
            issueA(c + 1, b ^ 1);
            CP_COMMIT();
            ldgB(c + 1);
        }
        const char* Ab = smem + (b ? OFF_A1 : OFF_A0);
        const char* Bb = smem + (b ? OFF_B1 : OFF_B0);
#pragma unroll
        for (int ks = 0; ks < 4; ks++) {
            uint32_t af[2][4];
#pragma unroll
            for (int mi = 0; mi < 2; mi++) {
                const char* p = Ab + (arow + mi * 16) * AS + (ks * 16 + acol) * 2;
                af[mi][0] = *reinterpret_cast<const uint32_t*>(p);
                af[mi][1] = *reinterpret_cast<const uint32_t*>(p + 8 * AS);
                af[mi][2] = *reinterpret_cast<const uint32_t*>(p + 16);
                af[mi][3] = *reinterpret_cast<const uint32_t*>(p + 8 * AS + 16);
            }
            uint32_t bfr[12][2];
#pragma unroll
            for (int ni = 0; ni < 12; ni++) {
                const char* p = Bb + (ni * 8 + (l >> 2)) * AS + (ks * 16 + acol) * 2;
                bfr[ni][0] = *reinterpret_cast<const uint32_t*>(p);
                bfr[ni][1] = *reinterpret_cast<const uint32_t*>(p + 16);
            }
#pragma unroll
            for (int ni = 0; ni < 12; ni++)
#pragma unroll
                for (int mi = 0; mi < 2; mi++)
                    mma_bf16(acc[mi][ni][0], acc[mi][ni][1], acc[mi][ni][2], acc[mi][ni][3],
                             af[mi][0], af[mi][1], af[mi][2], af[mi][3],
                             bfr[ni][0], bfr[ni][1]);
        }
        if (c < NCHUNKS - 1) {
            stsB(b ^ 1);
            CP_WAIT0();
        }
        __syncthreads();
    }

    // ---- per-row 1/||w||: reduce ssq across the 16 threads sharing a row
    float* INV = reinterpret_cast<float*>(smem + SMEM_INV);
#pragma unroll
    for (int i = 0; i < 6; i++) {
        float v = ssq[i];
        v += __shfl_xor_sync(0xffffffffu, v, 8);
        v += __shfl_xor_sync(0xffffffffu, v, 4);
        v += __shfl_xor_sync(0xffffffffu, v, 2);
        v += __shfl_xor_sync(0xffffffffu, v, 1);
        if ((tid & 15) == 0) INV[rb + i * 16] = 1.0f / fmaxf(sqrtf(v), 1e-12f);
    }
    __syncthreads();

    // ---- scale by 1/||w|| and write cosines to SMEM [sample][wrow]
    float* cosb = reinterpret_cast<float*>(smem + SMEM_BUF);
#pragma unroll
    for (int mi = 0; mi < 2; mi++) {
        int r0 = w * 32 + mi * 16 + (l >> 2);
#pragma unroll
        for (int ni = 0; ni < 12; ni++) {
            int n0 = ni * 8 + (l & 3) * 2;
            float i0 = INV[n0], i1 = INV[n0 + 1];
            cosb[r0 * COS_STRIDE + n0]           = acc[mi][ni][0] * i0;
            cosb[r0 * COS_STRIDE + n0 + 1]       = acc[mi][ni][1] * i1;
            cosb[(r0 + 8) * COS_STRIDE + n0]     = acc[mi][ni][2] * i0;
            cosb[(r0 + 8) * COS_STRIDE + n0 + 1] = acc[mi][ni][3] * i1;
        }
    }
    __syncthreads();

    // ---- per-sample epilogue: max-of-3 subcenters, margin, poly-exp partial sum
    const int s = tid;
    const int lab = is64 ? labels32[2 * s] : labels32[s];
    const int cls0 = cta * CLS_TILE;
    const float* crow = cosb + s * COS_STRIDE;
    float S = 0.0f;
#pragma unroll
    for (int j = 0; j < CLS_TILE; j++) {
        float c0 = crow[j * 3], c1 = crow[j * 3 + 1], c2 = crow[j * 3 + 2];
        float cosv = fmaxf(c0, fmaxf(c1, c2));
        if (cls0 + j == lab) {
            float sine = sqrtf(fmaxf(1.0f - cosv * cosv, 0.0f));
            float phi = cosv * 0.8775825618903728f - sine * 0.479425538604203f;
            if (!(cosv > -0.8775825618903728f)) phi = cosv - 0.2397127693021015f;
            g_LL[s] = 64.0f * phi;
            S += expshift(phi);
        } else {
            S += expshift(cosv);
        }
    }
    g_Spart[(size_t)cta * BATCH + s] = S;
}

// ---------------- kernel 3: per-sample logsumexp reduce ----------------
__global__ void __launch_bounds__(128) k_red() {
    int n = blockIdx.x, tid = threadIdx.x;
    float s = 0.0f;
    for (int i = tid; i < NCTAS; i += 128) s += g_Spart[(size_t)i * BATCH + n];
    s += __shfl_xor_sync(0xffffffffu, s, 16);
    s += __shfl_xor_sync(0xffffffffu, s, 8);
    s += __shfl_xor_sync(0xffffffffu, s, 4);
    s += __shfl_xor_sync(0xffffffffu, s, 2);
    s += __shfl_xor_sync(0xffffffffu, s, 1);
    __shared__ float ws[4];
    if ((tid & 31) == 0) ws[tid >> 5] = s;
    __syncthreads();
    if (tid == 0) {
        float t = ws[0] + ws[1] + ws[2] + ws[3];
        g_loss[n] = 64.0f + logf(t) - g_LL[n];
    }
}

// ---------------- kernel 4: mean ----------------
__global__ void __launch_bounds__(256) k_mean(float* __restrict__ out) {
    __shared__ float sm[256];
    int tid = threadIdx.x;
    sm[tid] = g_loss[tid];
    __syncthreads();
    for (int s = 128; s > 0; s >>= 1) {
        if (tid < s) sm[tid] += sm[tid + s];
        __syncthreads();
    }
    if (tid == 0) out[0] = sm[0] * (1.0f / BATCH);
}

// ---------------- launch ----------------
extern "C" void kernel_launch(void* const* d_in, const int* in_sizes, int n_in,
                              void* d_out, int out_size) {
    const float* E = (const float*)d_in[0];
    const int* labels = (const int*)d_in[1];
    const float* W = (const float*)d_in[2];
    cudaFuncSetAttribute(k_main, cudaFuncAttributeMaxDynamicSharedMemorySize, SMEM_TOTAL);
    k_norm_e<<<BATCH, 128>>>(E);
    k_main<<<NCTAS, 256, SMEM_TOTAL>>>(W, labels);
    k_red<<<BATCH, 128>>>();
    k_mean<<<1, 256>>>((float*)d_out);
}

// round 6
// speedup vs baseline: 1.3418x; 1.3418x over previous
#include <cuda_runtime.h>
#include <cuda_bf16.h>
#include <cstdint>

#define BATCH    256
#define EMB      512
#define NCLS     100000
#define N_TILE   96          // weight rows per CTA (32 classes)
#define CLS_TILE 32
#define NCTAS    3125
#define KCH      64          // K per chunk
#define NCHUNKS  8
#define NTHREADS 512

// SMEM: XOR-swizzled 128B rows (no padding)
#define A_BUF     (256 * 128)            // 32768
#define B_BUF     (96 * 128)             // 12288
#define SMEM_INV  0                      // 96 floats
#define SMEM_BUF  512
#define OFF_A0    (SMEM_BUF)
#define OFF_A1    (SMEM_BUF + A_BUF)
#define OFF_B0    (SMEM_BUF + 2 * A_BUF)
#define OFF_B1    (SMEM_BUF + 2 * A_BUF + B_BUF)
#define COS_STRIDE 97
#define COS_BYTES  (256 * COS_STRIDE * 4)      // 99328 (unions over GEMM bufs)
#define SMEM_TOTAL (SMEM_BUF + COS_BYTES)      // 99840

__device__ __forceinline__ uint32_t swz(uint32_t o) { return o ^ ((o >> 3) & 0x70); }

// device scratch
__device__ __align__(128) __nv_bfloat16 g_Ebf[BATCH * EMB];
__device__ float g_Spart[(size_t)NCTAS * 2 * BATCH];
__device__ float g_LL[BATCH];
__device__ float g_loss[BATCH];

// ---------------- helpers ----------------
__device__ __forceinline__ void cp_async16(uint32_t smem_dst, const void* gsrc) {
    asm volatile("cp.async.cg.shared.global [%0], [%1], 16;" :: "r"(smem_dst), "l"(gsrc));
}
#define CP_COMMIT() asm volatile("cp.async.commit_group;" ::: "memory")
#define CP_WAIT0()  asm volatile("cp.async.wait_group 0;" ::: "memory")

__device__ __forceinline__ void ldsm_x4(uint32_t& r0, uint32_t& r1, uint32_t& r2, uint32_t& r3,
                                        uint32_t addr) {
    asm volatile("ldmatrix.sync.aligned.m8n8.x4.shared.b16 {%0,%1,%2,%3}, [%4];"
                 : "=r"(r0), "=r"(r1), "=r"(r2), "=r"(r3) : "r"(addr));
}
__device__ __forceinline__ void ldsm_x2(uint32_t& r0, uint32_t& r1, uint32_t addr) {
    asm volatile("ldmatrix.sync.aligned.m8n8.x2.shared.b16 {%0,%1}, [%2];"
                 : "=r"(r0), "=r"(r1) : "r"(addr));
}

__device__ __forceinline__ void mma_bf16(float& d0, float& d1, float& d2, float& d3,
                                         uint32_t a0, uint32_t a1, uint32_t a2, uint32_t a3,
                                         uint32_t b0, uint32_t b1) {
    asm volatile("mma.sync.aligned.m16n8k16.row.col.f32.bf16.bf16.f32 "
                 "{%0,%1,%2,%3}, {%4,%5,%6,%7}, {%8,%9}, {%0,%1,%2,%3};"
                 : "+f"(d0), "+f"(d1), "+f"(d2), "+f"(d3)
                 : "r"(a0), "r"(a1), "r"(a2), "r"(a3), "r"(b0), "r"(b1));
}

// exp(64*(c-1)) via exp2 with degree-7 FFMA polynomial (no MUFU)
__device__ __forceinline__ float expshift(float c) {
    float x = 92.33248261689366f * (c - 1.0f);
    float t = fmaxf(x, -126.0f);
    float fl = floorf(t);
    float f = t - fl;
    float p = 1.5252733804059841e-5f;
    p = fmaf(p, f, 1.5403530393381608e-4f);
    p = fmaf(p, f, 1.3333558146428443e-3f);
    p = fmaf(p, f, 9.618129107628477e-3f);
    p = fmaf(p, f, 5.550410866482158e-2f);
    p = fmaf(p, f, 2.402265069591007e-1f);
    p = fmaf(p, f, 6.931471805599453e-1f);
    p = fmaf(p, f, 1.0f);
    return p * __int_as_float(((int)fl + 127) << 23);
}

// ---------------- kernel 1: normalize embeddings -> bf16 ----------------
__global__ void __launch_bounds__(128) k_norm_e(const float* __restrict__ E) {
    int n = blockIdx.x, tid = threadIdx.x;
    float4 v = *reinterpret_cast<const float4*>(E + n * EMB + tid * 4);
    float ss = v.x * v.x + v.y * v.y + v.z * v.z + v.w * v.w;
    ss += __shfl_xor_sync(0xffffffffu, ss, 16);
    ss += __shfl_xor_sync(0xffffffffu, ss, 8);
    ss += __shfl_xor_sync(0xffffffffu, ss, 4);
    ss += __shfl_xor_sync(0xffffffffu, ss, 2);
    ss += __shfl_xor_sync(0xffffffffu, ss, 1);
    __shared__ float ws[4];
    if ((tid & 31) == 0) ws[tid >> 5] = ss;
    __syncthreads();
    float inv = 1.0f / fmaxf(sqrtf(ws[0] + ws[1] + ws[2] + ws[3]), 1e-12f);
    uint32_t p0, p1;
    asm("cvt.rn.bf16x2.f32 %0, %1, %2;" : "=r"(p0) : "f"(v.y * inv), "f"(v.x * inv));
    asm("cvt.rn.bf16x2.f32 %0, %1, %2;" : "=r"(p1) : "f"(v.w * inv), "f"(v.z * inv));
    reinterpret_cast<uint2*>(g_Ebf)[n * (EMB / 4) + tid] = make_uint2(p0, p1);
}

// ---------------- kernel 2: GEMM (ldmatrix + mma.sync) + fused epilogue ----
__global__ void __launch_bounds__(NTHREADS) k_main(const float* __restrict__ W,
                                                   const int* __restrict__ labels32) {
    extern __shared__ char smem[];
    const uint32_t smem_sh = (uint32_t)__cvta_generic_to_shared(smem);
    const int tid = threadIdx.x;
    const int l = tid & 31, wid = tid >> 5;
    const int warp_m = wid & 3;          // M block: 64 rows
    const int warp_n = wid >> 2;         // N block: 24 rows
    const int cta = blockIdx.x;

    // label dtype probe: int64 iff all odd 32-bit words in first 1024B are 0
    int oddv = (tid < 128) ? labels32[2 * tid + 1] : 0;
    int is64 = (__syncthreads_or(oddv) == 0);

    // B loader mapping: 512 threads, col4 = tid&15 (float4 col), rowset = tid>>4 (0..31)
    const int col4 = tid & 15;
    const int rowset = tid >> 4;
    const float4* __restrict__ Wf4 = reinterpret_cast<const float4*>(W);

    float ssq[3] = {0.0f, 0.0f, 0.0f};

    float acc[4][3][4];
#pragma unroll
    for (int mi = 0; mi < 4; mi++)
#pragma unroll
        for (int nf = 0; nf < 3; nf++)
#pragma unroll
            for (int k = 0; k < 4; k++) acc[mi][nf][k] = 0.0f;

    // A copy: thread t -> sample row t/2, half t&1 (64B = 4x cp.async16)
    auto issueA = [&](int c, int buf) {
        int row = tid >> 1, half = tid & 1;
        uint32_t base = smem_sh + (buf ? OFF_A1 : OFF_A0);
        const char* src = reinterpret_cast<const char*>(g_Ebf)
                        + ((size_t)row * EMB + c * KCH + half * 32) * 2;
#pragma unroll
        for (int j = 0; j < 4; j++)
            cp_async16(base + swz(row * 128 + half * 64 + j * 16), src + j * 16);
    };
    // B prefetch to regs (3 float4 per thread)
    float4 bp[3];
    auto ldgB = [&](int c) {
#pragma unroll
        for (int i = 0; i < 3; i++) {
            size_t row = (size_t)cta * N_TILE + rowset + i * 32;
            bp[i] = Wf4[row * 128 + c * 16 + col4];
        }
    };
    // B cvt + ssq + STS (swizzled)
    auto stsB = [&](int buf) {
        char* base = smem + (buf ? OFF_B1 : OFF_B0);
#pragma unroll
        for (int i = 0; i < 3; i++) {
            float4 v = bp[i];
            ssq[i] = fmaf(v.x, v.x, fmaf(v.y, v.y, fmaf(v.z, v.z, fmaf(v.w, v.w, ssq[i]))));
            uint32_t p0, p1;
            asm("cvt.rn.bf16x2.f32 %0, %1, %2;" : "=r"(p0) : "f"(v.y), "f"(v.x));
            asm("cvt.rn.bf16x2.f32 %0, %1, %2;" : "=r"(p1) : "f"(v.w), "f"(v.z));
            *reinterpret_cast<uint2*>(base + swz((rowset + i * 32) * 128 + col4 * 8))
                = make_uint2(p0, p1);
        }
    };

    // prologue: chunk 0
    issueA(0, 0);
    CP_COMMIT();
    ldgB(0);
    stsB(0);
    CP_WAIT0();
    __syncthreads();

    // ldmatrix lane address components (constant parts)
    const int a_row_lane = (l & 15);            // + warp_m*64 + mi*16
    const int a_kb_lane  = (l >> 4) * 16;       // + ks*32
    const int b4_row_lane = (l & 7) + ((l >> 4) & 1) * 8;   // x4: rows 0..15
    const int b2_row_lane = 16 + (l & 7);                   // x2: rows 16..23
    const int b_kb_lane  = ((l >> 3) & 1) * 16;             // + ks*32

    for (int c = 0; c < NCHUNKS; c++) {
        int b = c & 1;
        if (c < NCHUNKS - 1) {
            issueA(c + 1, b ^ 1);
            CP_COMMIT();
            ldgB(c + 1);
        }
        uint32_t Ab = smem_sh + (b ? OFF_A1 : OFF_A0);
        uint32_t Bb = smem_sh + (b ? OFF_B1 : OFF_B0);
#pragma unroll
        for (int ks = 0; ks < 4; ks++) {
            uint32_t af[4][4];
#pragma unroll
            for (int mi = 0; mi < 4; mi++) {
                int row = warp_m * 64 + mi * 16 + a_row_lane;
                ldsm_x4(af[mi][0], af[mi][1], af[mi][2], af[mi][3],
                        Ab + swz(row * 128 + ks * 32 + a_kb_lane));
            }
            uint32_t bfr[3][2];
            {
                int row4 = warp_n * 24 + b4_row_lane;
                ldsm_x4(bfr[0][0], bfr[0][1], bfr[1][0], bfr[1][1],
                        Bb + swz(row4 * 128 + ks * 32 + b_kb_lane));
                int row2 = warp_n * 24 + b2_row_lane;
                ldsm_x2(bfr[2][0], bfr[2][1],
                        Bb + swz(row2 * 128 + ks * 32 + b_kb_lane));
            }
#pragma unroll
            for (int nf = 0; nf < 3; nf++)
#pragma unroll
                for (int mi = 0; mi < 4; mi++)
                    mma_bf16(acc[mi][nf][0], acc[mi][nf][1], acc[mi][nf][2], acc[mi][nf][3],
                             af[mi][0], af[mi][1], af[mi][2], af[mi][3],
                             bfr[nf][0], bfr[nf][1]);
        }
        if (c < NCHUNKS - 1) {
            stsB(b ^ 1);
            CP_WAIT0();
        }
        __syncthreads();
    }

    // per-row 1/||w||: reduce ssq across the 16 threads sharing rowset
    float* INV = reinterpret_cast<float*>(smem + SMEM_INV);
#pragma unroll
    for (int i = 0; i < 3; i++) {
        float v = ssq[i];
        v += __shfl_xor_sync(0xffffffffu, v, 8);
        v += __shfl_xor_sync(0xffffffffu, v, 4);
        v += __shfl_xor_sync(0xffffffffu, v, 2);
        v += __shfl_xor_sync(0xffffffffu, v, 1);
        if ((tid & 15) == 0) INV[rowset + i * 32] = 1.0f / fmaxf(sqrtf(v), 1e-12f);
    }
    __syncthreads();

    // scale by 1/||w||, stage cosines to SMEM [sample][wrow]
    float* cosb = reinterpret_cast<float*>(smem + SMEM_BUF);
#pragma unroll
    for (int mi = 0; mi < 4; mi++) {
        int r0 = warp_m * 64 + mi * 16 + (l >> 2);
#pragma unroll
        for (int nf = 0; nf < 3; nf++) {
            int n0 = warp_n * 24 + nf * 8 + (l & 3) * 2;
            float i0 = INV[n0], i1 = INV[n0 + 1];
            cosb[r0 * COS_STRIDE + n0]           = acc[mi][nf][0] * i0;
            cosb[r0 * COS_STRIDE + n0 + 1]       = acc[mi][nf][1] * i1;
            cosb[(r0 + 8) * COS_STRIDE + n0]     = acc[mi][nf][2] * i0;
            cosb[(r0 + 8) * COS_STRIDE + n0 + 1] = acc[mi][nf][3] * i1;
        }
    }
    __syncthreads();

    // per-sample epilogue: 512 threads = 256 samples x 2 halves of 16 classes
    const int s = tid & 255;
    const int half = tid >> 8;
    const int lab = is64 ? labels32[2 * s] : labels32[s];
    const int cls0 = cta * CLS_TILE + half * 16;
    const float* crow = cosb + s * COS_STRIDE + half * 48;
    float S = 0.0f;
#pragma unroll
    for (int j = 0; j < 16; j++) {
        float c0 = crow[j * 3], c1 = crow[j * 3 + 1], c2 = crow[j * 3 + 2];
        float cosv = fmaxf(c0, fmaxf(c1, c2));
        if (cls0 + j == lab) {
            float sine = sqrtf(fmaxf(1.0f - cosv * cosv, 0.0f));
            float phi = cosv * 0.8775825618903728f - sine * 0.479425538604203f;
            if (!(cosv > -0.8775825618903728f)) phi = cosv - 0.2397127693021015f;
            g_LL[s] = 64.0f * phi;
            S += expshift(phi);
        } else {
            S += expshift(cosv);
        }
    }
    g_Spart[((size_t)cta * 2 + half) * BATCH + s] = S;
}

// ---------------- kernel 3: per-sample logsumexp reduce ----------------
__global__ void __launch_bounds__(128) k_red() {
    int n = blockIdx.x, tid = threadIdx.x;
    float s = 0.0f;
    for (int i = tid; i < NCTAS * 2; i += 128) s += g_Spart[(size_t)i * BATCH + n];
    s += __shfl_xor_sync(0xffffffffu, s, 16);
    s += __shfl_xor_sync(0xffffffffu, s, 8);
    s += __shfl_xor_sync(0xffffffffu, s, 4);
    s += __shfl_xor_sync(0xffffffffu, s, 2);
    s += __shfl_xor_sync(0xffffffffu, s, 1);
    __shared__ float ws[4];
    if ((tid & 31) == 0) ws[tid >> 5] = s;
    __syncthreads();
    if (tid == 0) {
        float t = ws[0] + ws[1] + ws[2] + ws[3];
        g_loss[n] = 64.0f + logf(t) - g_LL[n];
    }
}

// ---------------- kernel 4: mean ----------------
__global__ void __launch_bounds__(256) k_mean(float* __restrict__ out) {
    __shared__ float sm[256];
    int tid = threadIdx.x;
    sm[tid] = g_loss[tid];
    __syncthreads();
    for (int s = 128; s > 0; s >>= 1) {
        if (tid < s) sm[tid] += sm[tid + s];
        __syncthreads();
    }
    if (tid == 0) out[0] = sm[0] * (1.0f / BATCH);
}

// ---------------- launch ----------------
extern "C" void kernel_launch(void* const* d_in, const int* in_sizes, int n_in,
                              void* d_out, int out_size) {
    const float* E = (const float*)d_in[0];
    const int* labels = (const int*)d_in[1];
    const float* W = (const float*)d_in[2];
    cudaFuncSetAttribute(k_main, cudaFuncAttributeMaxDynamicSharedMemorySize, SMEM_TOTAL);
    k_norm_e<<<BATCH, 128>>>(E);
    k_main<<<NCTAS, NTHREADS, SMEM_TOTAL>>>(W, labels);
    k_red<<<BATCH, 128>>>();
    k_mean<<<1, 256>>>((float*)d_out);
}